// round 1
// baseline (speedup 1.0000x reference)
#include <cuda_runtime.h>
#include <math.h>

#define NT 365
#define NS 1024
#define NH 64
#define NG 32
#define NW 514          // NH*8 + 2
#define SITES_PER_BLOCK 8
#define THREADS 256

// Scratch for the gate pre-activations w[s][j] (allocation-free rule: __device__ global)
__device__ float g_w[NS * NW];

__device__ __forceinline__ float sigm(float x) { return 1.0f / (1.0f + expf(-x)); }

// ---------------------------------------------------------------------------
// Kernel B: w = xc @ fc_w.T + fc_b   ([NS, NW])
// Grid 128 blocks x 8 sites, 256 threads. fc_w staged in shared in two passes
// of 257 rows (padded to 33 floats/row -> conflict-free LDS).
// ---------------------------------------------------------------------------
__global__ void gates_kernel(const float* __restrict__ xc,
                             const float* __restrict__ fc_w,
                             const float* __restrict__ fc_b) {
    __shared__ float sh_w[257 * 33];
    __shared__ float sh_xc[SITES_PER_BLOCK * NG];

    const int tid = threadIdx.x;
    const int s0  = blockIdx.x * SITES_PER_BLOCK;

    for (int i = tid; i < SITES_PER_BLOCK * NG; i += THREADS)
        sh_xc[i] = xc[s0 * NG + i];

    for (int pass = 0; pass < 2; ++pass) {
        const int jbase = pass * 257;
        __syncthreads();
        // stage 257 rows of fc_w (coalesced reads, padded shared rows)
        for (int i = tid; i < 257 * NG; i += THREADS) {
            int j = i >> 5, k = i & 31;
            sh_w[j * 33 + k] = fc_w[(jbase + j) * NG + k];
        }
        __syncthreads();
        // each thread computes some (site, j) outputs
        for (int o = tid; o < SITES_PER_BLOCK * 257; o += THREADS) {
            int si = o / 257;
            int jl = o - si * 257;
            float acc = 0.0f;
            #pragma unroll
            for (int k = 0; k < NG; ++k)
                acc += sh_xc[si * NG + k] * sh_w[jl * 33 + k];
            int j = jbase + jl;
            g_w[(s0 + si) * NW + j] = acc + fc_b[j];
        }
    }
}

// ---------------------------------------------------------------------------
// Kernel C: the sequential scan. One warp per site, 2 hidden units per lane.
// Forcing (Ps, Pl, Ta, E) for the block's 8 sites x 365 steps is staged into
// static shared (46.7 KB), with the arccos rain/snow partition computed during
// staging. Main loop: 1 broadcast LDS.128 + register math + 5-shuffle reduce.
// ---------------------------------------------------------------------------
__global__ void __launch_bounds__(THREADS)
scan_kernel(const float* __restrict__ x, float* __restrict__ out) {
    __shared__ float4 sForc[NT * SITES_PER_BLOCK];   // 46720 bytes

    const int tid  = threadIdx.x;
    const int s0   = blockIdx.x * SITES_PER_BLOCK;
    const int warp = tid >> 5;
    const int lane = tid & 31;
    const int s    = s0 + warp;

    // ---- Stage forcing + rain/snow partition ----
    const float4* x4 = reinterpret_cast<const float4*>(x);
    for (int i = tid; i < NT * SITES_PER_BLOCK; i += THREADS) {
        int t = i >> 3, si = i & 7;
        float4 xi = x4[t * NS + s0 + si];
        float P = xi.x, E = xi.y, T1 = xi.z, T2 = xi.w;
        float Ta = (T1 + T2) * 0.5f;
        bool valid  = (T1 < 0.0f) && (T2 > 0.0f);
        float denom = valid ? (T2 - T1) : 1.0f;
        float ratio = valid ? (T1 + T2) / denom : 0.0f;
        ratio = fminf(fmaxf(ratio, -0.999999f), 0.999999f);
        float rP = 1.0f - acosf(ratio) / 3.1415f;
        if (T1 >= 0.0f) rP = 1.0f;
        if (T2 <= 0.0f) rP = 0.0f;
        float4 o;
        o.x = (1.0f - rP) * P;   // Ps (snow)
        o.y = rP * P;            // Pl (liquid)
        o.z = Ta;
        o.w = E;
        sForc[i] = o;
    }

    // ---- Per-(site, h) gate activations (pure register work, no smem) ----
    const float* wrow = g_w + s * NW;
    float gm[2], ge[2], go[2], gl[2], ga[2], gb[2], gb1[2], kb[2], gi[2], araw[2];
    #pragma unroll
    for (int u = 0; u < 2; ++u) {
        int h = lane + u * 32;
        float w0 = wrow[0 * NH + h];
        float w1 = wrow[1 * NH + h];
        float w2 = wrow[2 * NH + h];
        float w3 = wrow[3 * NH + h];
        float w4 = wrow[4 * NH + h];
        float w5 = wrow[5 * NH + h];
        float w6 = wrow[6 * NH + h];
        float w7 = wrow[7 * NH + h];
        gm[u]   = expf(w0) + 1.0f;
        ge[u]   = 2.0f * sigm(w1);
        go[u]   = sigm(w2);
        gl[u]   = expf(2.0f * w3);
        araw[u] = w4;
        gb[u]   = sigm(w5);
        gb1[u]  = 1.0f - gb[u];
        kb[u]   = sigm(w6) * 0.1f;
        gi[u]   = sigm(w7);
    }
    // softmax over the 64 h values (2 per lane, warp reductions)
    float m = fmaxf(araw[0], araw[1]);
    #pragma unroll
    for (int o = 16; o; o >>= 1) m = fmaxf(m, __shfl_xor_sync(0xffffffffu, m, o));
    float e0 = expf(araw[0] - m), e1 = expf(araw[1] - m);
    float ssum = e0 + e1;
    #pragma unroll
    for (int o = 16; o; o >>= 1) ssum += __shfl_xor_sync(0xffffffffu, ssum, o);
    float inv = 1.0f / ssum;
    ga[0] = e0 * inv;
    ga[1] = e1 * inv;
    const float qb = fmaxf(wrow[NW - 1], 0.0f) * (1.0f / 64.0f);

    __syncthreads();

    // ---- Sequential scan: state in registers ----
    float S0[2] = {0.0f, 0.0f}, H0[2] = {0.0f, 0.0f}, G0[2] = {0.0f, 0.0f};

    #pragma unroll 2
    for (int t = 0; t < NT; ++t) {
        float4 f = sForc[t * SITES_PER_BLOCK + warp];   // broadcast LDS.128
        float y = 0.0f;
        #pragma unroll
        for (int u = 0; u < 2; ++u) {
            float S   = S0[u] + f.x;
            float Sm  = fminf(S0[u], fmaxf(f.z * gm[u], 0.0f));
            float H   = fmaxf(H0[u] + Sm + f.y * gi[u] - f.w * ge[u], 0.0f);
            float Q1  = fmaxf(H - gl[u], 0.0f);
            float Q2a = fminf(H, gl[u]) * go[u];
            float G   = G0[u] + Q2a * gb[u];
            float Q3  = G * kb[u];
            H0[u] = fminf(H - Q2a, gl[u]);
            G0[u] = G - Q3;
            S0[u] = S - Sm;
            y += (Q1 + Q2a * gb1[u] + Q3) * ga[u];
        }
        #pragma unroll
        for (int o = 16; o; o >>= 1) y += __shfl_xor_sync(0xffffffffu, y, o);
        if (lane == 0) out[t * NS + s] = y + qb;   // softmax sums to 1 => +qb once
    }
}

// ---------------------------------------------------------------------------
extern "C" void kernel_launch(void* const* d_in, const int* in_sizes, int n_in,
                              void* d_out, int out_size) {
    const float* x    = (const float*)d_in[0];   // [NT, NS, 4]
    const float* xc   = (const float*)d_in[1];   // [NS, NG]
    const float* fc_w = (const float*)d_in[2];   // [NW, NG]
    const float* fc_b = (const float*)d_in[3];   // [NW]
    float* out = (float*)d_out;                  // [NT, NS]

    gates_kernel<<<NS / SITES_PER_BLOCK, THREADS>>>(xc, fc_w, fc_b);
    scan_kernel<<<NS / SITES_PER_BLOCK, THREADS>>>(x, out);
}

// round 3
// speedup vs baseline: 1.3987x; 1.3987x over previous
#include <cuda_runtime.h>
#include <math.h>

#define NT 365
#define NS 1024
#define NH 64
#define NG 32
#define NW 514          // NH*8 + 2
#define PITCH 17        // partial-sum row pitch (conflict-free)

// Scratch for gate pre-activations w[s][j]
__device__ float g_w[NS * NW];

__device__ __forceinline__ float sigm(float x) { return 1.0f / (1.0f + expf(-x)); }

// ---------------------------------------------------------------------------
// Gates: w = xc @ fc_w.T + fc_b.  128 blocks x 256 threads, 8 sites/block.
// xc for the thread's site lives in registers; fc_w staged in padded shared
// (pitch 33 -> conflict-free). Inner MAC is 1 LDS + 1 FFMA.
// ---------------------------------------------------------------------------
__global__ void __launch_bounds__(256)
gates_kernel(const float* __restrict__ xc,
             const float* __restrict__ fc_w,
             const float* __restrict__ fc_b) {
    __shared__ float sh_w[258 * 33];

    const int tid  = threadIdx.x;
    const int lane = tid & 31;
    const int si   = tid >> 5;
    const int s    = blockIdx.x * 8 + si;

    float xr[32];
    {
        const float4* xc4 = reinterpret_cast<const float4*>(xc + s * NG);
        #pragma unroll
        for (int q = 0; q < 8; ++q) {
            float4 v = xc4[q];
            xr[q * 4 + 0] = v.x; xr[q * 4 + 1] = v.y;
            xr[q * 4 + 2] = v.z; xr[q * 4 + 3] = v.w;
        }
    }

    #pragma unroll
    for (int pass = 0; pass < 2; ++pass) {
        const int rbase = pass ? 256 : 0;
        const int rcnt  = pass ? 258 : 256;
        __syncthreads();
        for (int i = tid; i < rcnt * NG; i += 256) {
            int r = i >> 5, k = i & 31;
            sh_w[r * 33 + k] = fc_w[(rbase + r) * NG + k];
        }
        __syncthreads();
        const int clo = pass ? 8 : 0;
        const int chi = pass ? 17 : 8;
        for (int c = clo; c < chi; ++c) {
            int j = lane + 32 * c;
            if (j < NW) {
                const float* row = sh_w + (j - rbase) * 33;
                float acc = 0.0f;
                #pragma unroll
                for (int k = 0; k < NG; ++k)
                    acc += xr[k] * row[k];
                g_w[s * NW + j] = acc + fc_b[j];
            }
        }
    }
}

// ---------------------------------------------------------------------------
// Scan: one 32-thread block per site; lane l holds h=l and h=l+32.
// In-loop: LDS.128 forcing, register math, ONE shfl_xor(16), STS of 16
// partial sums (no result latency). Post-loop pass reduces the 16 partials
// per timestep and writes out. No deep shuffle chains -> no SB serialization.
// ---------------------------------------------------------------------------
__global__ void __launch_bounds__(32)
scan_kernel(const float* __restrict__ x, float* __restrict__ out) {
    __shared__ float4 sForc[NT];            // 5840 B
    __shared__ float  sPart[NT * PITCH];    // 24820 B

    const int lane = threadIdx.x;
    const int s    = blockIdx.x;

    // ---- stage forcing + rain/snow partition (12 LDG.128 per lane) ----
    const float4* x4 = reinterpret_cast<const float4*>(x);
    for (int t = lane; t < NT; t += 32) {
        float4 xi = x4[t * NS + s];
        float P = xi.x, E = xi.y, T1 = xi.z, T2 = xi.w;
        float Ta = (T1 + T2) * 0.5f;
        bool valid  = (T1 < 0.0f) && (T2 > 0.0f);
        float denom = valid ? (T2 - T1) : 1.0f;
        float ratio = valid ? (T1 + T2) / denom : 0.0f;
        ratio = fminf(fmaxf(ratio, -0.999999f), 0.999999f);
        float rP = 1.0f - acosf(ratio) / 3.1415f;
        if (T1 >= 0.0f) rP = 1.0f;
        if (T2 <= 0.0f) rP = 0.0f;
        float4 o;
        o.x = (1.0f - rP) * P;   // Ps
        o.y = rP * P;            // Pl
        o.z = Ta;
        o.w = E;
        sForc[t] = o;
    }

    // ---- per-(site,h) gate constants ----
    const float* wrow = g_w + s * NW;
    float gm[2], nge[2], go[2], gl[2], ga[2], kb1[2], gi[2], chc[2], cg[2];
    float araw[2], gb[2], kb[2];
    #pragma unroll
    for (int u = 0; u < 2; ++u) {
        int h = lane + u * 32;
        float w0 = wrow[0 * NH + h];
        float w1 = wrow[1 * NH + h];
        float w2 = wrow[2 * NH + h];
        float w3 = wrow[3 * NH + h];
        float w4 = wrow[4 * NH + h];
        float w5 = wrow[5 * NH + h];
        float w6 = wrow[6 * NH + h];
        float w7 = wrow[7 * NH + h];
        gm[u]   = expf(w0) + 1.0f;
        nge[u]  = -2.0f * sigm(w1);
        go[u]   = sigm(w2);
        gl[u]   = expf(2.0f * w3);
        araw[u] = w4;
        gb[u]   = sigm(w5);
        kb[u]   = sigm(w6) * 0.1f;
        gi[u]   = sigm(w7);
        kb1[u]  = 1.0f - kb[u];
    }
    // softmax over 64 h (outside the loop; shuffle trees are fine here)
    float m = fmaxf(araw[0], araw[1]);
    #pragma unroll
    for (int o = 16; o; o >>= 1) m = fmaxf(m, __shfl_xor_sync(0xffffffffu, m, o));
    float e0 = expf(araw[0] - m), e1 = expf(araw[1] - m);
    float ssum = e0 + e1;
    #pragma unroll
    for (int o = 16; o; o >>= 1) ssum += __shfl_xor_sync(0xffffffffu, ssum, o);
    float inv = 1.0f / ssum;
    ga[0] = e0 * inv;
    ga[1] = e1 * inv;
    #pragma unroll
    for (int u = 0; u < 2; ++u) {
        chc[u] = go[u] * (1.0f - gb[u]) * ga[u] - ga[u];  // coeff of Hc
        cg[u]  = kb[u] * ga[u];                           // coeff of g2
    }
    const float qb = fmaxf(wrow[NW - 1], 0.0f) * (1.0f / 64.0f);

    __syncwarp();

    // ---- sequential scan: state in registers, 1 shuffle + 1 STS per step ----
    float S0[2] = {0.f, 0.f}, H0[2] = {0.f, 0.f}, G0[2] = {0.f, 0.f};

    #pragma unroll 4
    for (int t = 0; t < NT; ++t) {
        float4 f = sForc[t];
        float y = 0.0f;
        #pragma unroll
        for (int u = 0; u < 2; ++u) {
            float mt  = fmaxf(f.z * gm[u], 0.0f);
            float Sm  = fminf(S0[u], mt);
            float At  = fmaf(f.w, nge[u], f.y * gi[u]);    // Pl*gi - E*ge
            float B   = Sm + At;
            float H   = fmaxf(H0[u] + B, 0.0f);
            float Hc  = fminf(H, gl[u]);
            float t1  = fmaf(-go[u], Hc, H);               // H - Q2a
            float Q2a = Hc * go[u];
            float g2  = fmaf(Q2a, gb[u], G0[u]);
            H0[u] = fminf(t1, gl[u]);
            G0[u] = g2 * kb1[u];
            S0[u] = (S0[u] - Sm) + f.x;
            y = fmaf(H, ga[u], y);
            y = fmaf(Hc, chc[u], y);
            y = fmaf(g2, cg[u], y);
        }
        y += __shfl_xor_sync(0xffffffffu, y, 16);          // one shuffle only
        if (lane < 16) sPart[t * PITCH + lane] = y;        // issue-only STS
    }

    __syncwarp();

    // ---- post-pass: sum 16 partials per t, write out (conflict-free) ----
    for (int i = lane; i < NT; i += 32) {
        const float* row = sPart + i * PITCH;
        float acc = qb;
        #pragma unroll
        for (int k = 0; k < 16; ++k) acc += row[k];
        out[i * NS + s] = acc;
    }
}

// ---------------------------------------------------------------------------
extern "C" void kernel_launch(void* const* d_in, const int* in_sizes, int n_in,
                              void* d_out, int out_size) {
    const float* x    = (const float*)d_in[0];   // [NT, NS, 4]
    const float* xc   = (const float*)d_in[1];   // [NS, NG]
    const float* fc_w = (const float*)d_in[2];   // [NW, NG]
    const float* fc_b = (const float*)d_in[3];   // [NW]
    float* out = (float*)d_out;                  // [NT, NS]

    gates_kernel<<<NS / 8, 256>>>(xc, fc_w, fc_b);
    scan_kernel<<<NS, 32>>>(x, out);
}